// round 7
// baseline (speedup 1.0000x reference)
#include <cuda_runtime.h>
#include <math.h>

#define N  2048
#define DH 256
#define DK 64
#define FF 32

// Scratch (static __device__ globals — allocation-free per harness rules)
__device__ float g_q[N * DK];
__device__ float g_k[N * DK];
__device__ float g_v[N * DH];
__device__ float g_s[(size_t)N * N];   // scores
__device__ float g_f[(size_t)N * N];   // focus (softmax weights)

// ---------------------------------------------------------------------------
// Kernel 1: q = x@Wq+bq, k = x@Wk+bk, v = x@Wv+bv
// 8 rows of x per block; each weight matrix is streamed once per block.
// ---------------------------------------------------------------------------
__global__ void __launch_bounds__(256) qkv_kernel(
    const float* __restrict__ x,
    const float* __restrict__ Wq, const float* __restrict__ bq,
    const float* __restrict__ Wk, const float* __restrict__ bk,
    const float* __restrict__ Wv, const float* __restrict__ bv) {
  __shared__ float xs[8][DH];
  const int t  = threadIdx.x;
  const int r0 = blockIdx.x * 8;

#pragma unroll
  for (int r = 0; r < 8; r++) xs[r][t] = x[(r0 + r) * DH + t];
  __syncthreads();

  // v: each thread owns output column t for 8 rows
  float acc[8];
#pragma unroll
  for (int r = 0; r < 8; r++) acc[r] = 0.f;
  for (int d = 0; d < DH; d++) {
    float w = Wv[d * DH + t];
#pragma unroll
    for (int r = 0; r < 8; r++) acc[r] = fmaf(xs[r][d], w, acc[r]);
  }
  float bvt = bv[t];
#pragma unroll
  for (int r = 0; r < 8; r++) g_v[(r0 + r) * DH + t] = acc[r] + bvt;

  // q (threads 0..63) and k (threads 64..127)
  if (t < 128) {
    const float* W = (t < 64) ? Wq : Wk;
    const float* b = (t < 64) ? bq : bk;
    float* outp    = (t < 64) ? g_q : g_k;
    const int c = t & 63;
    float a2[8];
#pragma unroll
    for (int r = 0; r < 8; r++) a2[r] = 0.f;
    for (int d = 0; d < DH; d++) {
      float w = W[d * DK + c];
#pragma unroll
      for (int r = 0; r < 8; r++) a2[r] = fmaf(xs[r][d], w, a2[r]);
    }
    float bb = b[c];
#pragma unroll
    for (int r = 0; r < 8; r++) outp[(r0 + r) * DK + c] = a2[r] + bb;
  }
}

// ---------------------------------------------------------------------------
// Kernel 2: S[i,j] = <k_i, q_j>   (64x64 tile per block, K = 64)
// ---------------------------------------------------------------------------
__global__ void __launch_bounds__(256) scores_kernel() {
  __shared__ float Ks[64][65];
  __shared__ float Qs[64][65];
  const int t  = threadIdx.x;
  const int tx = t & 15, ty = t >> 4;
  const int j0 = blockIdx.x * 64, i0 = blockIdx.y * 64;

#pragma unroll
  for (int p = 0; p < 16; p++) {
    int idx = t + p * 256;          // 4096 elements
    int c = idx & 63, il = idx >> 6;
    Ks[il][c] = g_k[(i0 + il) * DK + c];
    Qs[il][c] = g_q[(j0 + il) * DK + c];
  }
  __syncthreads();

  float acc[4][4];
#pragma unroll
  for (int r = 0; r < 4; r++)
#pragma unroll
    for (int c = 0; c < 4; c++) acc[r][c] = 0.f;

#pragma unroll 16
  for (int c = 0; c < 64; c++) {
    float rk[4], rq[4];
#pragma unroll
    for (int r = 0; r < 4; r++) rk[r] = Ks[ty * 4 + r][c];
#pragma unroll
    for (int q = 0; q < 4; q++) rq[q] = Qs[tx * 4 + q][c];
#pragma unroll
    for (int r = 0; r < 4; r++)
#pragma unroll
      for (int q = 0; q < 4; q++) acc[r][q] = fmaf(rk[r], rq[q], acc[r][q]);
  }

#pragma unroll
  for (int r = 0; r < 4; r++)
#pragma unroll
    for (int q = 0; q < 4; q++)
      g_s[(size_t)(i0 + ty * 4 + r) * N + j0 + tx * 4 + q] = acc[r][q];
}

// ---------------------------------------------------------------------------
// Kernel 3: per-pair MLP + row softmax.  One block per row i.
// Layer-1 fused into layer-2's k-loop so only 2x32 accumulators live in regs.
// ---------------------------------------------------------------------------
__global__ void __launch_bounds__(256) mlp_softmax_kernel(
    const float* __restrict__ adj, const float* __restrict__ dense,
    const float* __restrict__ W1, const float* __restrict__ b1,
    const float* __restrict__ W2, const float* __restrict__ b2,
    const float* __restrict__ W3, const float* __restrict__ b3) {
  __shared__ float4 w1p[FF];          // (W1[0,n], W1[1,n], W1[2,n], b1[n])
  __shared__ float  w2s[FF][FF];
  __shared__ float  w3s[FF];
  __shared__ float  b2s[FF];
  __shared__ float  lg[N];
  __shared__ float  red[8];

  const int t = threadIdx.x;
  const int i = blockIdx.x;

  if (t < FF) {
    w1p[t] = make_float4(W1[t], W1[FF + t], W1[2 * FF + t], b1[t]);
    w3s[t] = W3[t];
    b2s[t] = b2[t];
  }
  for (int idx = t; idx < FF * FF; idx += 256)
    w2s[idx >> 5][idx & 31] = W2[idx];
  const float b3v = b3[0];
  __syncthreads();

  const float* srow = g_s  + (size_t)i * N;
  const float* arow = adj  + (size_t)i * N;
  const float* drow = dense + (size_t)i * N;

  for (int jb = 0; jb < N; jb += 512) {   // 2 j's per thread per iter
    const int j0 = jb + t, j1 = j0 + 256;
    const float s0 = srow[j0], a0 = arow[j0], e0 = drow[j0];
    const float s1 = srow[j1], a1 = arow[j1], e1 = drow[j1];

    float acc0[FF], acc1[FF];
#pragma unroll
    for (int n = 0; n < FF; n++) { float bb = b2s[n]; acc0[n] = bb; acc1[n] = bb; }

#pragma unroll
    for (int k = 0; k < FF; k++) {
      const float4 w = w1p[k];
      const float h0 = fmaxf(fmaf(s0, w.x, fmaf(a0, w.y, fmaf(e0, w.z, w.w))), 0.f);
      const float h1 = fmaxf(fmaf(s1, w.x, fmaf(a1, w.y, fmaf(e1, w.z, w.w))), 0.f);
      const float4* w2row = reinterpret_cast<const float4*>(&w2s[k][0]);
#pragma unroll
      for (int n4 = 0; n4 < 8; n4++) {
        const float4 wv = w2row[n4];
        acc0[n4 * 4 + 0] = fmaf(h0, wv.x, acc0[n4 * 4 + 0]);
        acc0[n4 * 4 + 1] = fmaf(h0, wv.y, acc0[n4 * 4 + 1]);
        acc0[n4 * 4 + 2] = fmaf(h0, wv.z, acc0[n4 * 4 + 2]);
        acc0[n4 * 4 + 3] = fmaf(h0, wv.w, acc0[n4 * 4 + 3]);
        acc1[n4 * 4 + 0] = fmaf(h1, wv.x, acc1[n4 * 4 + 0]);
        acc1[n4 * 4 + 1] = fmaf(h1, wv.y, acc1[n4 * 4 + 1]);
        acc1[n4 * 4 + 2] = fmaf(h1, wv.z, acc1[n4 * 4 + 2]);
        acc1[n4 * 4 + 3] = fmaf(h1, wv.w, acc1[n4 * 4 + 3]);
      }
    }

    float l0 = b3v, l1 = b3v;
#pragma unroll
    for (int n = 0; n < FF; n++) {
      const float wn = w3s[n];
      l0 = fmaf(fmaxf(acc0[n], 0.f), wn, l0);
      l1 = fmaf(fmaxf(acc1[n], 0.f), wn, l1);
    }
    lg[j0] = l0;
    lg[j1] = l1;
  }
  __syncthreads();

  // ---- row softmax over lg[0..N) ----
  float m = -3.402823466e38f;
#pragma unroll
  for (int p = 0; p < 8; p++) m = fmaxf(m, lg[t + p * 256]);
#pragma unroll
  for (int o = 16; o > 0; o >>= 1) m = fmaxf(m, __shfl_xor_sync(0xffffffffu, m, o));
  if ((t & 31) == 0) red[t >> 5] = m;
  __syncthreads();
  float mm = red[0];
#pragma unroll
  for (int r = 1; r < 8; r++) mm = fmaxf(mm, red[r]);

  float sum = 0.f;
#pragma unroll
  for (int p = 0; p < 8; p++) {
    int j = t + p * 256;
    float e = __expf(lg[j] - mm);
    lg[j] = e;
    sum += e;
  }
#pragma unroll
  for (int o = 16; o > 0; o >>= 1) sum += __shfl_xor_sync(0xffffffffu, sum, o);
  __syncthreads();                 // everyone done reading red (max)
  if ((t & 31) == 0) red[t >> 5] = sum;
  __syncthreads();
  float tot = 0.f;
#pragma unroll
  for (int r = 0; r < 8; r++) tot += red[r];
  const float inv = 1.f / tot;

  float* frow = g_f + (size_t)i * N;
#pragma unroll
  for (int p = 0; p < 8; p++) {
    int j = t + p * 256;
    frow[j] = lg[j] * inv;
  }
}

// ---------------------------------------------------------------------------
// Kernel 4: out = focus @ v    (64x64 output tile per block, K-step 32)
// ---------------------------------------------------------------------------
__global__ void __launch_bounds__(256) out_kernel(float* __restrict__ outp) {
  __shared__ float Fs[32][65];
  __shared__ float Vs[32][65];
  const int t  = threadIdx.x;
  const int tx = t & 15, ty = t >> 4;
  const int d0 = blockIdx.x * 64;
  const int i0 = blockIdx.y * 64;

  float acc[4][4];
#pragma unroll
  for (int r = 0; r < 4; r++)
#pragma unroll
    for (int c = 0; c < 4; c++) acc[r][c] = 0.f;

  for (int k0 = 0; k0 < N; k0 += 32) {
#pragma unroll
    for (int p = 0; p < 8; p++) {
      int idx = t + p * 256;        // 2048 elements each
      int kk = idx & 31, il = idx >> 5;
      Fs[kk][il] = g_f[(size_t)(i0 + il) * N + k0 + kk];
      int dl = idx & 63, k2 = idx >> 6;
      Vs[k2][dl] = g_v[(k0 + k2) * DH + d0 + dl];
    }
    __syncthreads();
#pragma unroll
    for (int kk = 0; kk < 32; kk++) {
      float rf[4], rv[4];
#pragma unroll
      for (int r = 0; r < 4; r++) rf[r] = Fs[kk][ty * 4 + r];
#pragma unroll
      for (int c = 0; c < 4; c++) rv[c] = Vs[kk][tx * 4 + c];
#pragma unroll
      for (int r = 0; r < 4; r++)
#pragma unroll
        for (int c = 0; c < 4; c++) acc[r][c] = fmaf(rf[r], rv[c], acc[r][c]);
    }
    __syncthreads();
  }

#pragma unroll
  for (int r = 0; r < 4; r++)
#pragma unroll
    for (int c = 0; c < 4; c++)
      outp[(size_t)(i0 + ty * 4 + r) * DH + d0 + tx * 4 + c] = acc[r][c];
}

// ---------------------------------------------------------------------------
extern "C" void kernel_launch(void* const* d_in, const int* in_sizes, int n_in,
                              void* d_out, int out_size) {
  const float* x     = (const float*)d_in[0];
  const float* adj   = (const float*)d_in[1];
  const float* dense = (const float*)d_in[2];
  const float* Wq    = (const float*)d_in[3];
  const float* bq    = (const float*)d_in[4];
  const float* Wk    = (const float*)d_in[5];
  const float* bk    = (const float*)d_in[6];
  const float* Wv    = (const float*)d_in[7];
  const float* bv    = (const float*)d_in[8];
  const float* W1    = (const float*)d_in[9];
  const float* b1    = (const float*)d_in[10];
  const float* W2    = (const float*)d_in[11];
  const float* b2    = (const float*)d_in[12];
  const float* W3    = (const float*)d_in[13];
  const float* b3    = (const float*)d_in[14];
  float* outp        = (float*)d_out;

  qkv_kernel<<<N / 8, 256>>>(x, Wq, bq, Wk, bk, Wv, bv);
  scores_kernel<<<dim3(N / 64, N / 64), 256>>>();
  mlp_softmax_kernel<<<N, 256>>>(adj, dense, W1, b1, W2, b2, W3, b3);
  out_kernel<<<dim3(DH / 64, N / 64), 256>>>(outp);
}

// round 8
// speedup vs baseline: 1.1161x; 1.1161x over previous
#include <cuda_runtime.h>
#include <math.h>

#define N  2048
#define DH 256
#define DK 64
#define FF 32
#define SPLITK 4

// Scratch (static __device__ globals — allocation-free per harness rules)
__device__ float g_q[N * DK];
__device__ float g_k[N * DK];
__device__ float g_v[N * DH];
__device__ float g_s[(size_t)N * N];                 // scores
__device__ float g_f[(size_t)N * N];                 // logits -> focus
__device__ float g_part[SPLITK * N * DH];            // split-K partials (8 MB)

// ---------------------------------------------------------------------------
// Kernel 1: q = x@Wq+bq, k = x@Wk+bk, v = x@Wv+bv
// ---------------------------------------------------------------------------
__global__ void __launch_bounds__(256) qkv_kernel(
    const float* __restrict__ x,
    const float* __restrict__ Wq, const float* __restrict__ bq,
    const float* __restrict__ Wk, const float* __restrict__ bk,
    const float* __restrict__ Wv, const float* __restrict__ bv) {
  __shared__ float xs[8][DH];
  const int t  = threadIdx.x;
  const int r0 = blockIdx.x * 8;

#pragma unroll
  for (int r = 0; r < 8; r++) xs[r][t] = x[(r0 + r) * DH + t];
  __syncthreads();

  float acc[8];
#pragma unroll
  for (int r = 0; r < 8; r++) acc[r] = 0.f;
  for (int d = 0; d < DH; d++) {
    float w = Wv[d * DH + t];
#pragma unroll
    for (int r = 0; r < 8; r++) acc[r] = fmaf(xs[r][d], w, acc[r]);
  }
  float bvt = bv[t];
#pragma unroll
  for (int r = 0; r < 8; r++) g_v[(r0 + r) * DH + t] = acc[r] + bvt;

  if (t < 128) {
    const float* W = (t < 64) ? Wq : Wk;
    const float* b = (t < 64) ? bq : bk;
    float* outp    = (t < 64) ? g_q : g_k;
    const int c = t & 63;
    float a2[8];
#pragma unroll
    for (int r = 0; r < 8; r++) a2[r] = 0.f;
    for (int d = 0; d < DH; d++) {
      float w = W[d * DK + c];
#pragma unroll
      for (int r = 0; r < 8; r++) a2[r] = fmaf(xs[r][d], w, a2[r]);
    }
    float bb = b[c];
#pragma unroll
    for (int r = 0; r < 8; r++) outp[(r0 + r) * DK + c] = a2[r] + bb;
  }
}

// ---------------------------------------------------------------------------
// Kernel 2: S[i,j] = <k_i, q_j>   (64x64 tile per block, K = 64)
// ---------------------------------------------------------------------------
__global__ void __launch_bounds__(256) scores_kernel() {
  __shared__ float Ks[64][65];
  __shared__ float Qs[64][65];
  const int t  = threadIdx.x;
  const int tx = t & 15, ty = t >> 4;
  const int j0 = blockIdx.x * 64, i0 = blockIdx.y * 64;

#pragma unroll
  for (int p = 0; p < 16; p++) {
    int idx = t + p * 256;
    int c = idx & 63, il = idx >> 6;
    Ks[il][c] = g_k[(i0 + il) * DK + c];
    Qs[il][c] = g_q[(j0 + il) * DK + c];
  }
  __syncthreads();

  float acc[4][4];
#pragma unroll
  for (int r = 0; r < 4; r++)
#pragma unroll
    for (int c = 0; c < 4; c++) acc[r][c] = 0.f;

#pragma unroll 16
  for (int c = 0; c < 64; c++) {
    float rk[4], rq[4];
#pragma unroll
    for (int r = 0; r < 4; r++) rk[r] = Ks[ty * 4 + r][c];
#pragma unroll
    for (int q = 0; q < 4; q++) rq[q] = Qs[tx * 4 + q][c];
#pragma unroll
    for (int r = 0; r < 4; r++)
#pragma unroll
      for (int q = 0; q < 4; q++) acc[r][q] = fmaf(rk[r], rq[q], acc[r][q]);
  }

#pragma unroll
  for (int r = 0; r < 4; r++)
#pragma unroll
    for (int q = 0; q < 4; q++)
      g_s[(size_t)(i0 + ty * 4 + r) * N + j0 + tx * 4 + q] = acc[r][q];
}

// ---------------------------------------------------------------------------
// Kernel 3a: per-pair MLP -> logits.  One pair per thread, grid-stride (8x).
// Minimal register state: acc[32] only.  Weights broadcast from smem.
// ---------------------------------------------------------------------------
#define LOGIT_IT 8
__global__ void __launch_bounds__(256) logits_kernel(
    const float* __restrict__ adj, const float* __restrict__ dense,
    const float* __restrict__ W1, const float* __restrict__ b1,
    const float* __restrict__ W2, const float* __restrict__ b2,
    const float* __restrict__ W3, const float* __restrict__ b3) {
  __shared__ float4 w1p[FF];          // (W1[0,n], W1[1,n], W1[2,n], b1[n])
  __shared__ float  w2s[FF][FF];
  __shared__ float  w3s[FF];
  __shared__ float  b2s[FF];

  const int t = threadIdx.x;
  if (t < FF) {
    w1p[t] = make_float4(W1[t], W1[FF + t], W1[2 * FF + t], b1[t]);
    w3s[t] = W3[t];
    b2s[t] = b2[t];
  }
  for (int idx = t; idx < FF * FF; idx += 256)
    w2s[idx >> 5][idx & 31] = W2[idx];
  const float b3v = b3[0];
  __syncthreads();

  const size_t stride = (size_t)gridDim.x * 256;     // = N*N / LOGIT_IT
  size_t idx = (size_t)blockIdx.x * 256 + t;

#pragma unroll 1
  for (int it = 0; it < LOGIT_IT; it++, idx += stride) {
    const float s = g_s[idx];
    const float a = adj[idx];
    const float e = dense[idx];

    float acc[FF];
#pragma unroll
    for (int n = 0; n < FF; n++) acc[n] = b2s[n];

#pragma unroll
    for (int k = 0; k < FF; k++) {
      const float4 w = w1p[k];
      const float h = fmaxf(fmaf(s, w.x, fmaf(a, w.y, fmaf(e, w.z, w.w))), 0.f);
      const float4* w2row = reinterpret_cast<const float4*>(&w2s[k][0]);
#pragma unroll
      for (int n4 = 0; n4 < 8; n4++) {
        const float4 wv = w2row[n4];
        acc[n4 * 4 + 0] = fmaf(h, wv.x, acc[n4 * 4 + 0]);
        acc[n4 * 4 + 1] = fmaf(h, wv.y, acc[n4 * 4 + 1]);
        acc[n4 * 4 + 2] = fmaf(h, wv.z, acc[n4 * 4 + 2]);
        acc[n4 * 4 + 3] = fmaf(h, wv.w, acc[n4 * 4 + 3]);
      }
    }

    float l = b3v;
#pragma unroll
    for (int n = 0; n < FF; n++)
      l = fmaf(fmaxf(acc[n], 0.f), w3s[n], l);
    g_f[idx] = l;
  }
}

// ---------------------------------------------------------------------------
// Kernel 3b: row softmax over logits (in place on g_f).  One block per row.
// ---------------------------------------------------------------------------
__global__ void __launch_bounds__(256) softmax_kernel() {
  __shared__ float red[8];
  const int t = threadIdx.x;
  float* row = g_f + (size_t)blockIdx.x * N;

  float v[8];
  float m = -3.402823466e38f;
#pragma unroll
  for (int p = 0; p < 8; p++) {
    v[p] = row[t + p * 256];
    m = fmaxf(m, v[p]);
  }
#pragma unroll
  for (int o = 16; o > 0; o >>= 1) m = fmaxf(m, __shfl_xor_sync(0xffffffffu, m, o));
  if ((t & 31) == 0) red[t >> 5] = m;
  __syncthreads();
  float mm = red[0];
#pragma unroll
  for (int r = 1; r < 8; r++) mm = fmaxf(mm, red[r]);
  __syncthreads();

  float sum = 0.f;
#pragma unroll
  for (int p = 0; p < 8; p++) {
    float e = __expf(v[p] - mm);
    v[p] = e;
    sum += e;
  }
#pragma unroll
  for (int o = 16; o > 0; o >>= 1) sum += __shfl_xor_sync(0xffffffffu, sum, o);
  if ((t & 31) == 0) red[t >> 5] = sum;
  __syncthreads();
  float tot = 0.f;
#pragma unroll
  for (int r = 0; r < 8; r++) tot += red[r];
  const float inv = 1.f / tot;

#pragma unroll
  for (int p = 0; p < 8; p++) row[t + p * 256] = v[p] * inv;
}

// ---------------------------------------------------------------------------
// Kernel 4a: partial out = focus @ v over a K-slice (split-K = 4)
// 64x64 output tile per block; grid (DH/64, N/64, SPLITK) = 512 blocks.
// ---------------------------------------------------------------------------
__global__ void __launch_bounds__(256) out_split_kernel() {
  __shared__ float Fs[32][65];
  __shared__ float Vs[32][65];
  const int t  = threadIdx.x;
  const int tx = t & 15, ty = t >> 4;
  const int d0 = blockIdx.x * 64;
  const int i0 = blockIdx.y * 64;
  const int kz = blockIdx.z;
  const int kbeg = kz * (N / SPLITK);
  const int kend = kbeg + (N / SPLITK);

  float acc[4][4];
#pragma unroll
  for (int r = 0; r < 4; r++)
#pragma unroll
    for (int c = 0; c < 4; c++) acc[r][c] = 0.f;

  for (int k0 = kbeg; k0 < kend; k0 += 32) {
#pragma unroll
    for (int p = 0; p < 8; p++) {
      int idx = t + p * 256;
      int kk = idx & 31, il = idx >> 5;
      Fs[kk][il] = g_f[(size_t)(i0 + il) * N + k0 + kk];
      int dl = idx & 63, k2 = idx >> 6;
      Vs[k2][dl] = g_v[(k0 + k2) * DH + d0 + dl];
    }
    __syncthreads();
#pragma unroll
    for (int kk = 0; kk < 32; kk++) {
      float rf[4], rv[4];
#pragma unroll
      for (int r = 0; r < 4; r++) rf[r] = Fs[kk][ty * 4 + r];
#pragma unroll
      for (int c = 0; c < 4; c++) rv[c] = Vs[kk][tx * 4 + c];
#pragma unroll
      for (int r = 0; r < 4; r++)
#pragma unroll
        for (int c = 0; c < 4; c++) acc[r][c] = fmaf(rf[r], rv[c], acc[r][c]);
    }
    __syncthreads();
  }

  float* part = g_part + (size_t)kz * N * DH;
#pragma unroll
  for (int r = 0; r < 4; r++)
#pragma unroll
    for (int c = 0; c < 4; c++)
      part[(size_t)(i0 + ty * 4 + r) * DH + d0 + tx * 4 + c] = acc[r][c];
}

// ---------------------------------------------------------------------------
// Kernel 4b: reduce split-K partials into the output.
// ---------------------------------------------------------------------------
__global__ void __launch_bounds__(256) out_reduce_kernel(float* __restrict__ outp) {
  const size_t idx = (size_t)blockIdx.x * 256 + threadIdx.x;   // N*DH total
  float s = g_part[idx];
#pragma unroll
  for (int z = 1; z < SPLITK; z++) s += g_part[(size_t)z * N * DH + idx];
  outp[idx] = s;
}

// ---------------------------------------------------------------------------
extern "C" void kernel_launch(void* const* d_in, const int* in_sizes, int n_in,
                              void* d_out, int out_size) {
  const float* x     = (const float*)d_in[0];
  const float* adj   = (const float*)d_in[1];
  const float* dense = (const float*)d_in[2];
  const float* Wq    = (const float*)d_in[3];
  const float* bq    = (const float*)d_in[4];
  const float* Wk    = (const float*)d_in[5];
  const float* bk    = (const float*)d_in[6];
  const float* Wv    = (const float*)d_in[7];
  const float* bv    = (const float*)d_in[8];
  const float* W1    = (const float*)d_in[9];
  const float* b1    = (const float*)d_in[10];
  const float* W2    = (const float*)d_in[11];
  const float* b2    = (const float*)d_in[12];
  const float* W3    = (const float*)d_in[13];
  const float* b3    = (const float*)d_in[14];
  float* outp        = (float*)d_out;

  qkv_kernel<<<N / 8, 256>>>(x, Wq, bq, Wk, bk, Wv, bv);
  scores_kernel<<<dim3(N / 64, N / 64), 256>>>();
  logits_kernel<<<(N * N) / (256 * LOGIT_IT), 256>>>(adj, dense,
                                                     W1, b1, W2, b2, W3, b3);
  softmax_kernel<<<N, 256>>>();
  out_split_kernel<<<dim3(DH / 64, N / 64, SPLITK), 256>>>();
  out_reduce_kernel<<<(N * DH) / 256, 256>>>(outp);
}

// round 9
// speedup vs baseline: 10.9928x; 9.8494x over previous
#include <cuda_runtime.h>
#include <math.h>

#define N  2048
#define DH 256
#define DK 64
#define FF 32
#define SPLITK 4
#define TP 128            // pairs per logits block tile

// Scratch (static __device__ globals — allocation-free per harness rules)
__device__ float g_q[N * DK];
__device__ float g_k[N * DK];
__device__ float g_v[N * DH];
__device__ float g_s[(size_t)N * N];                 // scores
__device__ float g_f[(size_t)N * N];                 // logits -> focus
__device__ float g_part[SPLITK * N * DH];            // split-K partials

// ---------------------------------------------------------------------------
// Kernel 1: q = x@Wq+bq, k = x@Wk+bk, v = x@Wv+bv
// ---------------------------------------------------------------------------
__global__ void __launch_bounds__(256) qkv_kernel(
    const float* __restrict__ x,
    const float* __restrict__ Wq, const float* __restrict__ bq,
    const float* __restrict__ Wk, const float* __restrict__ bk,
    const float* __restrict__ Wv, const float* __restrict__ bv) {
  __shared__ float xs[8][DH];
  const int t  = threadIdx.x;
  const int r0 = blockIdx.x * 8;

#pragma unroll
  for (int r = 0; r < 8; r++) xs[r][t] = x[(r0 + r) * DH + t];
  __syncthreads();

  float acc[8];
#pragma unroll
  for (int r = 0; r < 8; r++) acc[r] = 0.f;
  for (int d = 0; d < DH; d++) {
    float w = Wv[d * DH + t];
#pragma unroll
    for (int r = 0; r < 8; r++) acc[r] = fmaf(xs[r][d], w, acc[r]);
  }
  float bvt = bv[t];
#pragma unroll
  for (int r = 0; r < 8; r++) g_v[(r0 + r) * DH + t] = acc[r] + bvt;

  if (t < 128) {
    const float* W = (t < 64) ? Wq : Wk;
    const float* b = (t < 64) ? bq : bk;
    float* outp    = (t < 64) ? g_q : g_k;
    const int c = t & 63;
    float a2[8];
#pragma unroll
    for (int r = 0; r < 8; r++) a2[r] = 0.f;
    for (int d = 0; d < DH; d++) {
      float w = W[d * DK + c];
#pragma unroll
      for (int r = 0; r < 8; r++) a2[r] = fmaf(xs[r][d], w, a2[r]);
    }
    float bb = b[c];
#pragma unroll
    for (int r = 0; r < 8; r++) outp[(r0 + r) * DK + c] = a2[r] + bb;
  }
}

// ---------------------------------------------------------------------------
// Kernel 2: S[i,j] = <k_i, q_j>   (64x64 tile per block, K = 64)
// ---------------------------------------------------------------------------
__global__ void __launch_bounds__(256) scores_kernel() {
  __shared__ float Ks[64][65];
  __shared__ float Qs[64][65];
  const int t  = threadIdx.x;
  const int tx = t & 15, ty = t >> 4;
  const int j0 = blockIdx.x * 64, i0 = blockIdx.y * 64;

#pragma unroll
  for (int p = 0; p < 16; p++) {
    int idx = t + p * 256;
    int c = idx & 63, il = idx >> 6;
    Ks[il][c] = g_k[(i0 + il) * DK + c];
    Qs[il][c] = g_q[(j0 + il) * DK + c];
  }
  __syncthreads();

  float acc[4][4];
#pragma unroll
  for (int r = 0; r < 4; r++)
#pragma unroll
    for (int c = 0; c < 4; c++) acc[r][c] = 0.f;

#pragma unroll 16
  for (int c = 0; c < 64; c++) {
    float rk[4], rq[4];
#pragma unroll
    for (int r = 0; r < 4; r++) rk[r] = Ks[ty * 4 + r][c];
#pragma unroll
    for (int q = 0; q < 4; q++) rq[q] = Qs[tx * 4 + q][c];
#pragma unroll
    for (int r = 0; r < 4; r++)
#pragma unroll
      for (int q = 0; q < 4; q++) acc[r][q] = fmaf(rk[r], rq[q], acc[r][q]);
  }

#pragma unroll
  for (int r = 0; r < 4; r++)
#pragma unroll
    for (int q = 0; q < 4; q++)
      g_s[(size_t)(i0 + ty * 4 + r) * N + j0 + tx * 4 + q] = acc[r][q];
}

// ---------------------------------------------------------------------------
// Kernel 3a: per-pair MLP -> logits, as a tiled GEMM.
// Block tile: TP=128 pairs x FF=32 outputs. 256 threads.
//   Phase A: h1T[k][p] = relu(W1 . (s,a,e) + b1)   (smem, transposed)
//   Phase B: outer-product GEMM, 4x4 register tile per thread
//   Phase C: +b2, relu, dot w3, 8-way smem reduction -> logit per pair
// No per-thread array exceeds 16 floats (avoids local-memory demotion).
// ---------------------------------------------------------------------------
__global__ void __launch_bounds__(256) logits_kernel(
    const float* __restrict__ adj, const float* __restrict__ dense,
    const float* __restrict__ W1, const float* __restrict__ b1,
    const float* __restrict__ W2, const float* __restrict__ b2,
    const float* __restrict__ W3, const float* __restrict__ b3) {
  __shared__ float ss[TP], aa[TP], ee[TP];
  __shared__ float h1T[FF][TP + 4];       // [k][p], row stride 132 (16B-aligned)
  __shared__ float w2s[FF][FF];           // [k][n]
  __shared__ float w1x[FF], w1y[FF], w1z[FF], b1s[FF], w3s[FF], b2s[FF];
  __shared__ float red[TP][9];

  const int t = threadIdx.x;
  const size_t base = (size_t)blockIdx.x * TP;

  if (t < FF) {
    w1x[t] = W1[t];
    w1y[t] = W1[FF + t];
    w1z[t] = W1[2 * FF + t];
    b1s[t] = b1[t];
    w3s[t] = W3[t];
    b2s[t] = b2[t];
  }
  for (int i = t; i < FF * FF; i += 256) w2s[i >> 5][i & 31] = W2[i];
  if (t < TP) {
    ss[t] = g_s[base + t];
    aa[t] = adj[base + t];
    ee[t] = dense[base + t];
  }
  const float b3v = b3[0];
  __syncthreads();

  // ---- Phase A: h1 ----
#pragma unroll
  for (int it = 0; it < (TP * FF) / 256; it++) {
    int idx = t + it * 256;
    int p = idx >> 5, k = idx & 31;
    float h = fmaf(ss[p], w1x[k], fmaf(aa[p], w1y[k], fmaf(ee[p], w1z[k], b1s[k])));
    h1T[k][p] = fmaxf(h, 0.f);
  }
  __syncthreads();

  // ---- Phase B: GEMM (128x32) = h1 (128x32) @ W2 (32x32) ----
  const int tx = t & 7;        // output cols tx*4 .. tx*4+3
  const int ty = t >> 3;       // pair rows  ty*4 .. ty*4+3   (0..31)

  float acc[4][4];
#pragma unroll
  for (int r = 0; r < 4; r++)
#pragma unroll
    for (int c = 0; c < 4; c++) acc[r][c] = 0.f;

#pragma unroll
  for (int k = 0; k < FF; k++) {
    const float4 rf = *reinterpret_cast<const float4*>(&h1T[k][ty * 4]);
    const float4 rw = *reinterpret_cast<const float4*>(&w2s[k][tx * 4]);
    acc[0][0] = fmaf(rf.x, rw.x, acc[0][0]);
    acc[0][1] = fmaf(rf.x, rw.y, acc[0][1]);
    acc[0][2] = fmaf(rf.x, rw.z, acc[0][2]);
    acc[0][3] = fmaf(rf.x, rw.w, acc[0][3]);
    acc[1][0] = fmaf(rf.y, rw.x, acc[1][0]);
    acc[1][1] = fmaf(rf.y, rw.y, acc[1][1]);
    acc[1][2] = fmaf(rf.y, rw.z, acc[1][2]);
    acc[1][3] = fmaf(rf.y, rw.w, acc[1][3]);
    acc[2][0] = fmaf(rf.z, rw.x, acc[2][0]);
    acc[2][1] = fmaf(rf.z, rw.y, acc[2][1]);
    acc[2][2] = fmaf(rf.z, rw.z, acc[2][2]);
    acc[2][3] = fmaf(rf.z, rw.w, acc[2][3]);
    acc[3][0] = fmaf(rf.w, rw.x, acc[3][0]);
    acc[3][1] = fmaf(rf.w, rw.y, acc[3][1]);
    acc[3][2] = fmaf(rf.w, rw.z, acc[3][2]);
    acc[3][3] = fmaf(rf.w, rw.w, acc[3][3]);
  }

  // ---- Phase C: epilogue + reduction ----
  const float bb0 = b2s[tx * 4 + 0], bb1 = b2s[tx * 4 + 1];
  const float bb2 = b2s[tx * 4 + 2], bb3 = b2s[tx * 4 + 3];
  const float ww0 = w3s[tx * 4 + 0], ww1 = w3s[tx * 4 + 1];
  const float ww2 = w3s[tx * 4 + 2], ww3 = w3s[tx * 4 + 3];
#pragma unroll
  for (int r = 0; r < 4; r++) {
    float pv = fmaxf(acc[r][0] + bb0, 0.f) * ww0;
    pv = fmaf(fmaxf(acc[r][1] + bb1, 0.f), ww1, pv);
    pv = fmaf(fmaxf(acc[r][2] + bb2, 0.f), ww2, pv);
    pv = fmaf(fmaxf(acc[r][3] + bb3, 0.f), ww3, pv);
    red[ty * 4 + r][tx] = pv;
  }
  __syncthreads();

  if (t < TP) {
    float l = b3v;
#pragma unroll
    for (int c = 0; c < 8; c++) l += red[t][c];
    g_f[base + t] = l;
  }
}

// ---------------------------------------------------------------------------
// Kernel 3b: row softmax over logits (in place on g_f).  One block per row.
// ---------------------------------------------------------------------------
__global__ void __launch_bounds__(256) softmax_kernel() {
  __shared__ float red[8];
  const int t = threadIdx.x;
  float* row = g_f + (size_t)blockIdx.x * N;

  float v[8];
  float m = -3.402823466e38f;
#pragma unroll
  for (int p = 0; p < 8; p++) {
    v[p] = row[t + p * 256];
    m = fmaxf(m, v[p]);
  }
#pragma unroll
  for (int o = 16; o > 0; o >>= 1) m = fmaxf(m, __shfl_xor_sync(0xffffffffu, m, o));
  if ((t & 31) == 0) red[t >> 5] = m;
  __syncthreads();
  float mm = red[0];
#pragma unroll
  for (int r = 1; r < 8; r++) mm = fmaxf(mm, red[r]);
  __syncthreads();

  float sum = 0.f;
#pragma unroll
  for (int p = 0; p < 8; p++) {
    float e = __expf(v[p] - mm);
    v[p] = e;
    sum += e;
  }
#pragma unroll
  for (int o = 16; o > 0; o >>= 1) sum += __shfl_xor_sync(0xffffffffu, sum, o);
  if ((t & 31) == 0) red[t >> 5] = sum;
  __syncthreads();
  float tot = 0.f;
#pragma unroll
  for (int r = 0; r < 8; r++) tot += red[r];
  const float inv = 1.f / tot;

#pragma unroll
  for (int p = 0; p < 8; p++) row[t + p * 256] = v[p] * inv;
}

// ---------------------------------------------------------------------------
// Kernel 4a: partial out = focus @ v over a K-slice (split-K = 4)
// ---------------------------------------------------------------------------
__global__ void __launch_bounds__(256) out_split_kernel() {
  __shared__ float Fs[32][65];
  __shared__ float Vs[32][65];
  const int t  = threadIdx.x;
  const int tx = t & 15, ty = t >> 4;
  const int d0 = blockIdx.x * 64;
  const int i0 = blockIdx.y * 64;
  const int kz = blockIdx.z;
  const int kbeg = kz * (N / SPLITK);
  const int kend = kbeg + (N / SPLITK);

  float acc[4][4];
#pragma unroll
  for (int r = 0; r < 4; r++)
#pragma unroll
    for (int c = 0; c < 4; c++) acc[r][c] = 0.f;

  for (int k0 = kbeg; k0 < kend; k0 += 32) {
#pragma unroll
    for (int p = 0; p < 8; p++) {
      int idx = t + p * 256;
      int kk = idx & 31, il = idx >> 5;
      Fs[kk][il] = g_f[(size_t)(i0 + il) * N + k0 + kk];
      int dl = idx & 63, k2 = idx >> 6;
      Vs[k2][dl] = g_v[(k0 + k2) * DH + d0 + dl];
    }
    __syncthreads();
#pragma unroll
    for (int kk = 0; kk < 32; kk++) {
      float rf[4], rv[4];
#pragma unroll
      for (int r = 0; r < 4; r++) rf[r] = Fs[kk][ty * 4 + r];
#pragma unroll
      for (int c = 0; c < 4; c++) rv[c] = Vs[kk][tx * 4 + c];
#pragma unroll
      for (int r = 0; r < 4; r++)
#pragma unroll
        for (int c = 0; c < 4; c++) acc[r][c] = fmaf(rf[r], rv[c], acc[r][c]);
    }
    __syncthreads();
  }

  float* part = g_part + (size_t)kz * N * DH;
#pragma unroll
  for (int r = 0; r < 4; r++)
#pragma unroll
    for (int c = 0; c < 4; c++)
      part[(size_t)(i0 + ty * 4 + r) * DH + d0 + tx * 4 + c] = acc[r][c];
}

// ---------------------------------------------------------------------------
// Kernel 4b: reduce split-K partials into the output.
// ---------------------------------------------------------------------------
__global__ void __launch_bounds__(256) out_reduce_kernel(float* __restrict__ outp) {
  const size_t idx = (size_t)blockIdx.x * 256 + threadIdx.x;
  float s = g_part[idx];
#pragma unroll
  for (int z = 1; z < SPLITK; z++) s += g_part[(size_t)z * N * DH + idx];
  outp[idx] = s;
}

// ---------------------------------------------------------------------------
extern "C" void kernel_launch(void* const* d_in, const int* in_sizes, int n_in,
                              void* d_out, int out_size) {
  const float* x     = (const float*)d_in[0];
  const float* adj   = (const float*)d_in[1];
  const float* dense = (const float*)d_in[2];
  const float* Wq    = (const float*)d_in[3];
  const float* bq    = (const float*)d_in[4];
  const float* Wk    = (const float*)d_in[5];
  const float* bk    = (const float*)d_in[6];
  const float* Wv    = (const float*)d_in[7];
  const float* bv    = (const float*)d_in[8];
  const float* W1    = (const float*)d_in[9];
  const float* b1    = (const float*)d_in[10];
  const float* W2    = (const float*)d_in[11];
  const float* b2    = (const float*)d_in[12];
  const float* W3    = (const float*)d_in[13];
  const float* b3    = (const float*)d_in[14];
  float* outp        = (float*)d_out;

  qkv_kernel<<<N / 8, 256>>>(x, Wq, bq, Wk, bk, Wv, bv);
  scores_kernel<<<dim3(N / 64, N / 64), 256>>>();
  logits_kernel<<<(N * N) / TP, 256>>>(adj, dense, W1, b1, W2, b2, W3, b3);
  softmax_kernel<<<N, 256>>>();
  out_split_kernel<<<dim3(DH / 64, N / 64, SPLITK), 256>>>();
  out_reduce_kernel<<<(N * DH) / 256, 256>>>(outp);
}